// round 7
// baseline (speedup 1.0000x reference)
#include <cuda_runtime.h>
#include <cuda_fp16.h>
#include <math.h>
#include <stdint.h>

#define NN   2048
#define RR   5
#define CC   2
#define DD   256
#define HD   128
#define NCLS 16

// ---------------- scratch (device globals, no allocations) ----------------
__device__ float g_F[6 * RR];
__device__ float g_H [CC * NN * NN];     // fp32 GEMM1 out
__device__ float g_H2[CC * NN * NN];     // fp32 GEMM2 out (normalized in place)
__device__ float g_part[CC * 16 * NN];
__device__ float g_deg [CC * NN];
__device__ float g_agg[CC * NN * DD];
__device__ float g_X  [CC * NN * HD];
__device__ float g_X2 [NN * HD];
// fp16 operands
__device__ __half g_Q0f[CC * NN * NN];   // A of GEMM1, row-major [m][k]
__device__ __half g_Q1f[CC * NN * NN];   // pre-transpose [k][n]
__device__ __half g_Q2f[CC * NN * NN];
__device__ __half g_Q1t[CC * NN * NN];   // B of GEMM1 [n][k]
__device__ __half g_Q2t[CC * NN * NN];   // B of GEMM2 [n][k]
__device__ __half g_Hf [CC * NN * NN];   // A of GEMM2, row-major [m][k]

// ================= PTX helpers (sm_100 base: cp.async + ldmatrix + mma.sync) ==
__device__ __forceinline__ uint32_t smem_u32(const void* p) {
    uint32_t a;
    asm("{ .reg .u64 t; cvta.to.shared.u64 t, %1; cvt.u32.u64 %0, t; }" : "=r"(a) : "l"(p));
    return a;
}
__device__ __forceinline__ void cpasync16(uint32_t dst, const void* src) {
    asm volatile("cp.async.cg.shared.global [%0], [%1], 16;" :: "r"(dst), "l"(src) : "memory");
}
__device__ __forceinline__ void cpasync_commit() {
    asm volatile("cp.async.commit_group;" ::: "memory");
}
template<int N> __device__ __forceinline__ void cpasync_wait() {
    asm volatile("cp.async.wait_group %0;" :: "n"(N) : "memory");
}
__device__ __forceinline__ void ldmx4(uint32_t* r, uint32_t a) {
    asm volatile("ldmatrix.sync.aligned.m8n8.x4.shared.b16 {%0,%1,%2,%3},[%4];"
        : "=r"(r[0]), "=r"(r[1]), "=r"(r[2]), "=r"(r[3]) : "r"(a));
}
__device__ __forceinline__ void ldmx2(uint32_t* r, uint32_t a) {
    asm volatile("ldmatrix.sync.aligned.m8n8.x2.shared.b16 {%0,%1},[%2];"
        : "=r"(r[0]), "=r"(r[1]) : "r"(a));
}
__device__ __forceinline__ void mma16(float* c, const uint32_t* a, const uint32_t* b) {
    asm volatile("mma.sync.aligned.m16n8k16.row.col.f32.f16.f16.f32 "
        "{%0,%1,%2,%3},{%4,%5,%6,%7},{%8,%9},{%0,%1,%2,%3};"
        : "+f"(c[0]), "+f"(c[1]), "+f"(c[2]), "+f"(c[3])
        : "r"(a[0]), "r"(a[1]), "r"(a[2]), "r"(a[3]), "r"(b[0]), "r"(b[1]));
}

// ================= fp16 tensor-core GEMM: C[M,N] = A[M,K] * B[N,K]^T ========
// M=N=K=2048. CTA tile 128x128, BK=64 (128B rows), 4-stage cp.async pipeline.
#define KT      32                 // 2048/64
#define STAGES  4
#define STG_SZ  32768              // A 16KB + B 16KB per stage
#define SMEM16  (STAGES * STG_SZ)

__global__ __launch_bounds__(256, 1) void gemm16_k(
    const __half* __restrict__ Ag, const __half* __restrict__ Bg,
    float* __restrict__ C)
{
    extern __shared__ char smem[];
    const uint32_t sb = smem_u32(smem);
    const int tid = threadIdx.x, lane = tid & 31, warp = tid >> 5;
    const int m0 = blockIdx.y * 128, n0 = blockIdx.x * 128;
    const long coff = (long)blockIdx.z * NN * NN;
    Ag += coff; Bg += coff; C += coff;
    const int wm = (warp >> 2) * 64;     // 2 warp rows
    const int wn = (warp & 3) * 32;      // 4 warp cols

    float acc[4][4][4];
    #pragma unroll
    for (int i = 0; i < 4; i++)
        #pragma unroll
        for (int j = 0; j < 4; j++)
            #pragma unroll
            for (int v = 0; v < 4; v++) acc[i][j][v] = 0.f;

    auto load_stage = [&](int st, int k0) {
        const uint32_t sa = sb + st * STG_SZ;
        const uint32_t sbm = sa + 16384;
        #pragma unroll
        for (int i = 0; i < 4; i++) {
            int id = i * 256 + tid;              // 0..1023
            int row = id >> 3, c = id & 7;
            uint32_t off = (uint32_t)row * 128 + (uint32_t)((c ^ (row & 7)) << 4);
            cpasync16(sa + off, Ag + (long)(m0 + row) * NN + k0 + c * 8);
            cpasync16(sbm + off, Bg + (long)(n0 + row) * NN + k0 + c * 8);
        }
        cpasync_commit();
    };

    #pragma unroll
    for (int s = 0; s < STAGES - 1; s++) load_stage(s, s * 64);

    for (int kt = 0; kt < KT; kt++) {
        {   // wait for stage kt's data
            const int rem = KT - 1 - kt;
            if      (rem >= 2) cpasync_wait<STAGES - 2>();
            else if (rem == 1) cpasync_wait<1>();
            else               cpasync_wait<0>();
        }
        __syncthreads();
        const int kn = kt + STAGES - 1;
        if (kn < KT) load_stage(kn & (STAGES - 1), kn * 64);

        const uint32_t sa = sb + (kt & (STAGES - 1)) * STG_SZ;
        const uint32_t sbm = sa + 16384;
        #pragma unroll
        for (int kk = 0; kk < 4; kk++) {
            uint32_t a[4][4], b[4][2];
            #pragma unroll
            for (int mi = 0; mi < 4; mi++) {
                int row = wm + mi * 16 + (lane & 15);
                int c = kk * 2 + (lane >> 4);
                ldmx4(a[mi], sa + row * 128 + ((c ^ (row & 7)) << 4));
            }
            #pragma unroll
            for (int ni = 0; ni < 4; ni++) {
                int row = wn + ni * 8 + (lane & 7);
                int c = kk * 2 + ((lane >> 3) & 1);
                ldmx2(b[ni], sbm + row * 128 + ((c ^ (row & 7)) << 4));
            }
            #pragma unroll
            for (int mi = 0; mi < 4; mi++)
                #pragma unroll
                for (int ni = 0; ni < 4; ni++)
                    mma16(acc[mi][ni], a[mi], b[ni]);
        }
        __syncthreads();
    }

    // epilogue: direct fp32 stores from fragments
    #pragma unroll
    for (int mi = 0; mi < 4; mi++) {
        #pragma unroll
        for (int ni = 0; ni < 4; ni++) {
            int r0 = m0 + wm + mi * 16 + (lane >> 2);
            int c0 = n0 + wn + ni * 8 + (lane & 3) * 2;
            float2 v0; v0.x = acc[mi][ni][0]; v0.y = acc[mi][ni][1];
            float2 v1; v1.x = acc[mi][ni][2]; v1.y = acc[mi][ni][3];
            *(float2*)&C[(long)r0 * NN + c0]       = v0;
            *(float2*)&C[(long)(r0 + 8) * NN + c0] = v1;
        }
    }
}

// ---------------- softmax over relations ----------------
__global__ void softmax_k(const float* __restrict__ W) {
    int t = threadIdx.x;
    if (t < 6) {
        const float* w = W + t * RR;
        float mx = w[0];
        #pragma unroll
        for (int r = 1; r < RR; r++) mx = fmaxf(mx, w[r]);
        float e[RR], s = 0.f;
        #pragma unroll
        for (int r = 0; r < RR; r++) { e[r] = expf(w[r] - mx); s += e[r]; }
        #pragma unroll
        for (int r = 0; r < RR; r++) g_F[t * RR + r] = e[r] / s;
    }
}

// ---------------- qcombine: all six F*A combos -> fp16 ----------------
__global__ __launch_bounds__(256) void qcombine_k(const float* __restrict__ A) {
    long i4 = ((long)blockIdx.x * blockDim.x + threadIdx.x) * 4;
    if (i4 >= (long)NN * NN) return;
    float4 a[RR];
    #pragma unroll
    for (int r = 0; r < RR; r++)
        a[r] = *(const float4*)&A[(long)r * NN * NN + i4];
    float f[6][RR];
    #pragma unroll
    for (int c = 0; c < 6; c++)
        #pragma unroll
        for (int r = 0; r < RR; r++) f[c][r] = g_F[c * RR + r];

    __half* outs[6] = { g_Q0f, g_Q0f + (long)NN * NN,
                        g_Q1f, g_Q1f + (long)NN * NN,
                        g_Q2f, g_Q2f + (long)NN * NN };
    #pragma unroll
    for (int c = 0; c < 6; c++) {
        float o[4] = {0.f, 0.f, 0.f, 0.f};
        #pragma unroll
        for (int r = 0; r < RR; r++) {
            o[0] = fmaf(f[c][r], a[r].x, o[0]);
            o[1] = fmaf(f[c][r], a[r].y, o[1]);
            o[2] = fmaf(f[c][r], a[r].z, o[2]);
            o[3] = fmaf(f[c][r], a[r].w, o[3]);
        }
        __half2* dst = (__half2*)&outs[c][i4];
        dst[0] = __halves2half2(__float2half_rn(o[0]), __float2half_rn(o[1]));
        dst[1] = __halves2half2(__float2half_rn(o[2]), __float2half_rn(o[3]));
    }
}

// ---------------- fp16 transpose: [k][n] -> [n][k] for Q1, Q2 ----------------
__global__ __launch_bounds__(256) void tsplit_k() {
    __shared__ __half t[32][34];
    int z = blockIdx.z;                                     // 0,1: Q1 ch ; 2,3: Q2 ch
    const __half* src = (z < 2 ? g_Q1f : g_Q2f) + (long)(z & 1) * NN * NN;
    __half* dst       = (z < 2 ? g_Q1t : g_Q2t) + (long)(z & 1) * NN * NN;
    int x0 = blockIdx.x * 32, y0 = blockIdx.y * 32;
    int tx = threadIdx.x & 31, ty = threadIdx.x >> 5;       // 32 x 8
    #pragma unroll
    for (int i = 0; i < 4; i++)
        t[ty + 8 * i][tx] = src[(long)(y0 + ty + 8 * i) * NN + x0 + tx];
    __syncthreads();
    #pragma unroll
    for (int i = 0; i < 4; i++) {
        int r = ty + 8 * i;
        dst[(long)(x0 + r) * NN + y0 + tx] = t[tx][r];
    }
}

// ---------------- SIMT SGEMM (agg / gcn tails) ----------------
template<bool TA, bool EPI>
__global__ __launch_bounds__(256) void sgemm_k(
    const float* __restrict__ A, const float* __restrict__ B,
    float* __restrict__ C, const float* __restrict__ bias,
    int M, int N, int K, long sA, long sB, long sC)
{
    constexpr int BM = 128, BN = 128, BK = 8;
    __shared__ float As[BK][BM];
    __shared__ float Bs[BK][BN];
    A += (long)blockIdx.z * sA;
    B += (long)blockIdx.z * sB;
    C += (long)blockIdx.z * sC;
    const int bm = blockIdx.y * BM, bn = blockIdx.x * BN;
    const int tid = threadIdx.x;
    const int tx = tid & 15, ty = tid >> 4;

    float acc[8][8];
    #pragma unroll
    for (int i = 0; i < 8; i++)
        #pragma unroll
        for (int j = 0; j < 8; j++) acc[i][j] = 0.f;

    for (int k0 = 0; k0 < K; k0 += BK) {
        if (!TA) {
            int row = tid >> 1;
            int col = (tid & 1) * 4;
            float4 v = *(const float4*)&A[(long)(bm + row) * K + k0 + col];
            As[col + 0][row] = v.x; As[col + 1][row] = v.y;
            As[col + 2][row] = v.z; As[col + 3][row] = v.w;
        } else {
            int kk = tid >> 5;
            int mm = (tid & 31) * 4;
            *(float4*)&As[kk][mm] = *(const float4*)&A[(long)(k0 + kk) * M + bm + mm];
        }
        {
            int kk = tid >> 5;
            int nn = (tid & 31) * 4;
            *(float4*)&Bs[kk][nn] = *(const float4*)&B[(long)(k0 + kk) * N + bn + nn];
        }
        __syncthreads();
        #pragma unroll
        for (int kk = 0; kk < BK; kk++) {
            float a[8], b[8];
            #pragma unroll
            for (int i = 0; i < 8; i++) a[i] = As[kk][ty * 8 + i];
            #pragma unroll
            for (int j = 0; j < 8; j++) b[j] = Bs[kk][tx * 8 + j];
            #pragma unroll
            for (int i = 0; i < 8; i++)
                #pragma unroll
                for (int j = 0; j < 8; j++)
                    acc[i][j] = fmaf(a[i], b[j], acc[i][j]);
        }
        __syncthreads();
    }

    #pragma unroll
    for (int i = 0; i < 8; i++) {
        long r = bm + ty * 8 + i;
        float* Crow = C + r * (long)N + bn + tx * 8;
        #pragma unroll
        for (int j = 0; j < 8; j += 4) {
            float4 v;
            float v0 = acc[i][j], v1 = acc[i][j + 1], v2 = acc[i][j + 2], v3 = acc[i][j + 3];
            if (EPI) {
                const float* bp = bias + bn + tx * 8 + j;
                v0 = fmaxf(v0 + bp[0], 0.f);
                v1 = fmaxf(v1 + bp[1], 0.f);
                v2 = fmaxf(v2 + bp[2], 0.f);
                v3 = fmaxf(v3 + bp[3], 0.f);
            }
            v.x = v0; v.y = v1; v.z = v2; v.w = v3;
            *(float4*)&Crow[j] = v;
        }
    }
}

// ---------------- column sums ----------------
__global__ __launch_bounds__(128) void colsum_part_k(const float* __restrict__ H) {
    int cg = blockIdx.x, jc = blockIdx.y;
    int col = cg * 128 + threadIdx.x;
    int c = col / NN, m = col % NN;
    const float* Hc = H + (long)c * NN * NN;
    float s = 0.f;
    int n0 = jc * 128;
    #pragma unroll 4
    for (int n = n0; n < n0 + 128; n++)
        s += Hc[(long)n * NN + m];
    g_part[(long)c * 16 * NN + (long)jc * NN + m] = s;
}
__global__ __launch_bounds__(128) void colsum_final_k(const float* __restrict__ H) {
    int idx = blockIdx.x * blockDim.x + threadIdx.x;
    if (idx >= CC * NN) return;
    int c = idx / NN, m = idx % NN;
    float s = 0.f;
    #pragma unroll
    for (int j = 0; j < 16; j++)
        s += g_part[(long)c * 16 * NN + (long)j * NN + m];
    s -= H[(long)c * NN * NN + (long)m * NN + m];
    g_deg[idx] = s;
}

// ---------------- mid norm -> fp16 A operand of GEMM2 ----------------
__global__ __launch_bounds__(256) void norm_mid_k(const float* __restrict__ H) {
    long i = (long)blockIdx.x * blockDim.x + threadIdx.x;
    if (i >= (long)CC * NN * NN) return;
    int c = (int)(i / ((long)NN * NN));
    long rem = i % ((long)NN * NN);
    int n = (int)(rem / NN), m = (int)(rem % NN);
    float d = g_deg[c * NN + m];
    float v = (n == m || d <= 0.f) ? 0.f : H[i] / d;
    g_Hf[i] = __float2half_rn(v);
}

// ---------------- final double normalization (fused) ----------------
__global__ __launch_bounds__(256) void norm_final_k(float* __restrict__ H) {
    long i = (long)blockIdx.x * blockDim.x + threadIdx.x;
    if (i >= (long)CC * NN * NN) return;
    int c = (int)(i / ((long)NN * NN));
    long rem = i % ((long)NN * NN);
    int n = (int)(rem / NN), m = (int)(rem % NN);
    float d1 = g_deg[c * NN + m];
    float d2 = (d1 > 0.f) ? 2.f : 1.f;
    float v;
    if (n == m)        v = 1.0f;
    else if (d1 > 0.f) v = H[i] / d1;
    else               v = 0.0f;
    H[i] = v / d2;
}

// ---------------- lin1 / lin2 ----------------
__global__ __launch_bounds__(128) void lin1_k(const float* __restrict__ w,
                                              const float* __restrict__ b) {
    __shared__ float xr[CC * HD];
    int m = blockIdx.x, t = threadIdx.x;
    xr[t]      = g_X[(long)m * HD + t];
    xr[HD + t] = g_X[(long)NN * HD + (long)m * HD + t];
    __syncthreads();
    float acc = b[t];
    #pragma unroll 8
    for (int k = 0; k < CC * HD; k++)
        acc = fmaf(xr[k], w[k * HD + t], acc);
    g_X2[(long)m * HD + t] = fmaxf(acc, 0.f);
}
__global__ __launch_bounds__(128) void lin2_k(const int* __restrict__ idx,
                                              const float* __restrict__ w,
                                              const float* __restrict__ b,
                                              float* __restrict__ y, int ncat) {
    int i = blockIdx.x * blockDim.x + threadIdx.x;
    if (i >= ncat * NCLS) return;
    int row = i / NCLS, j = i % NCLS;
    const float* x = g_X2 + (long)idx[row] * HD;
    float acc = b[j];
    #pragma unroll 8
    for (int k = 0; k < HD; k++)
        acc = fmaf(x[k], w[k * NCLS + j], acc);
    y[i] = acc;
}

// ---------------- launch ----------------
extern "C" void kernel_launch(void* const* d_in, const int* in_sizes, int n_in,
                              void* d_out, int out_size) {
    const float *A = 0, *h = 0, *W_conv = 0, *gcn_w = 0, *gcn_b = 0;
    const float *lin1_w = 0, *lin1_b = 0, *lin2_w = 0, *lin2_b = 0;
    const int* catidx = 0;
    int ncat = 0;
    for (int i = 0; i < n_in; i++) {
        int s = in_sizes[i];
        const void* p = d_in[i];
        if      (s == RR * NN * NN) A = (const float*)p;
        else if (s == NN * DD)      h = (const float*)p;
        else if (s == 3 * CC * RR)  W_conv = (const float*)p;
        else if (s == DD * HD) { if (!gcn_w) gcn_w = (const float*)p; else lin1_w = (const float*)p; }
        else if (s == HD)      { if (!gcn_b) gcn_b = (const float*)p; else lin1_b = (const float*)p; }
        else if (s == HD * NCLS) lin2_w = (const float*)p;
        else if (s == NCLS)      lin2_b = (const float*)p;
        else { catidx = (const int*)p; ncat = s; }
    }
    float* y = (float*)d_out;

    float *H, *H2, *agg, *X;
    __half *Q0f, *Q1t, *Q2t, *Hf;
    cudaGetSymbolAddress((void**)&H,   g_H);
    cudaGetSymbolAddress((void**)&H2,  g_H2);
    cudaGetSymbolAddress((void**)&agg, g_agg);
    cudaGetSymbolAddress((void**)&X,   g_X);
    cudaGetSymbolAddress((void**)&Q0f, g_Q0f);
    cudaGetSymbolAddress((void**)&Q1t, g_Q1t);
    cudaGetSymbolAddress((void**)&Q2t, g_Q2t);
    cudaGetSymbolAddress((void**)&Hf,  g_Hf);

    static int smem_set = 0;
    if (!smem_set) {
        cudaFuncSetAttribute(gemm16_k, cudaFuncAttributeMaxDynamicSharedMemorySize, SMEM16);
        smem_set = 1;
    }

    const long NNNN = (long)NN * NN;

    softmax_k<<<1, 32>>>(W_conv);
    qcombine_k<<<(int)(NNNN / 4 / 256), 256>>>(A);
    tsplit_k<<<dim3(NN / 32, NN / 32, 4), 256>>>();

    // GEMM1: H = Q0 @ Q1   (fp16 tensor cores, fp32 accum)
    gemm16_k<<<dim3(16, 16, CC), 256, SMEM16>>>(Q0f, Q1t, H);

    colsum_part_k<<<dim3(CC * NN / 128, 16), 128>>>(H);
    colsum_final_k<<<CC * NN / 128, 128>>>(H);
    norm_mid_k<<<(int)(CC * NNNN / 256), 256>>>(H);

    // GEMM2: H2 = Hn @ Q2
    gemm16_k<<<dim3(16, 16, CC), 256, SMEM16>>>(Hf, Q2t, H2);

    colsum_part_k<<<dim3(CC * NN / 128, 16), 128>>>(H2);
    colsum_final_k<<<CC * NN / 128, 128>>>(H2);
    norm_final_k<<<(int)(CC * NNNN / 256), 256>>>(H2);

    // agg[c,m,d] = sum_n Hs[c,n,m] * h[n,d]
    {
        dim3 g(DD / 128, NN / 128, CC);
        sgemm_k<true, false><<<g, 256>>>(H2, h, agg, nullptr,
                                         NN, DD, NN, NNNN, 0, (long)NN * DD);
    }
    // X = relu(agg @ gcn_w + gcn_b)
    {
        dim3 g(HD / 128, NN / 128, CC);
        sgemm_k<false, true><<<g, 256>>>(agg, gcn_w, X, gcn_b,
                                         NN, HD, DD, (long)NN * DD, 0, (long)NN * HD);
    }
    lin1_k<<<NN, 128>>>(lin1_w, lin1_b);
    lin2_k<<<(ncat * NCLS + 127) / 128, 128>>>(catidx, lin2_w, lin2_b, y, ncat);
}

// round 8
// speedup vs baseline: 1.8867x; 1.8867x over previous
#include <cuda_runtime.h>
#include <cuda_fp16.h>
#include <math.h>
#include <stdint.h>

#define NN   2048
#define RR   5
#define CC   2
#define DD   256
#define HD   128
#define NCLS 16

// ---------------- scratch (device globals, no allocations) ----------------
__device__ float g_F[6 * RR];
__device__ float g_H [CC * NN * NN];     // fp32 GEMM1 out
__device__ float g_H2[CC * NN * NN];     // fp32 GEMM2 out
__device__ float g_part[CC * 16 * NN];
__device__ float g_deg [CC * NN];
__device__ float g_agg[CC * NN * DD];
__device__ float g_X  [CC * NN * HD];
__device__ float g_X2 [NN * HD];
// fp16 operands
__device__ __half g_Q0f[CC * NN * NN];   // A of GEMM1, row-major [m][k]
__device__ __half g_Q1t[CC * NN * NN];   // B of GEMM1 [n][k]
__device__ __half g_Q2t[CC * NN * NN];   // B of GEMM2 [n][k]
__device__ __half g_Hf [CC * NN * NN];   // A of GEMM2, row-major [m][k]
__device__ __half g_HsT[CC * NN * NN];   // A of AGG: HsT[c][m][n] = Hs[c][n][m]
__device__ __half g_hT [DD * NN];        // B of AGG: hT[d][n] = h[n][d]

// ================= PTX helpers =================
__device__ __forceinline__ uint32_t smem_u32(const void* p) {
    uint32_t a;
    asm("{ .reg .u64 t; cvta.to.shared.u64 t, %1; cvt.u32.u64 %0, t; }" : "=r"(a) : "l"(p));
    return a;
}
__device__ __forceinline__ void cpasync16(uint32_t dst, const void* src) {
    asm volatile("cp.async.cg.shared.global [%0], [%1], 16;" :: "r"(dst), "l"(src) : "memory");
}
__device__ __forceinline__ void cpasync_commit() {
    asm volatile("cp.async.commit_group;" ::: "memory");
}
template<int N> __device__ __forceinline__ void cpasync_wait() {
    asm volatile("cp.async.wait_group %0;" :: "n"(N) : "memory");
}
__device__ __forceinline__ void ldmx4(uint32_t* r, uint32_t a) {
    asm volatile("ldmatrix.sync.aligned.m8n8.x4.shared.b16 {%0,%1,%2,%3},[%4];"
        : "=r"(r[0]), "=r"(r[1]), "=r"(r[2]), "=r"(r[3]) : "r"(a));
}
__device__ __forceinline__ void ldmx2(uint32_t* r, uint32_t a) {
    asm volatile("ldmatrix.sync.aligned.m8n8.x2.shared.b16 {%0,%1},[%2];"
        : "=r"(r[0]), "=r"(r[1]) : "r"(a));
}
__device__ __forceinline__ void mma16(float* c, const uint32_t* a, const uint32_t* b) {
    asm volatile("mma.sync.aligned.m16n8k16.row.col.f32.f16.f16.f32 "
        "{%0,%1,%2,%3},{%4,%5,%6,%7},{%8,%9},{%0,%1,%2,%3};"
        : "+f"(c[0]), "+f"(c[1]), "+f"(c[2]), "+f"(c[3])
        : "r"(a[0]), "r"(a[1]), "r"(a[2]), "r"(a[3]), "r"(b[0]), "r"(b[1]));
}

// ================= fp16 tensor-core GEMM: C[M,Ntile] = A[M,K] * B[N,K]^T ====
// lda = ldb = NN (2048). K = 2048. CTA tile 128x128, BK=64, 3-stage pipeline.
#define KT      32                 // 2048/64
#define STAGES  3
#define STG_SZ  32768              // A 16KB + B 16KB per stage
#define SMEM16  (STAGES * STG_SZ)

__global__ __launch_bounds__(256, 2) void gemm16_k(
    const __half* __restrict__ Ag, const __half* __restrict__ Bg,
    float* __restrict__ C, int ldc, long sA, long sB, long sC)
{
    extern __shared__ char smem[];
    const uint32_t sb = smem_u32(smem);
    const int tid = threadIdx.x, lane = tid & 31, warp = tid >> 5;
    const int m0 = blockIdx.y * 128, n0 = blockIdx.x * 128;
    Ag += (long)blockIdx.z * sA;
    Bg += (long)blockIdx.z * sB;
    C  += (long)blockIdx.z * sC;
    const int wm = (warp >> 2) * 64;
    const int wn = (warp & 3) * 32;

    float acc[4][4][4];
    #pragma unroll
    for (int i = 0; i < 4; i++)
        #pragma unroll
        for (int j = 0; j < 4; j++)
            #pragma unroll
            for (int v = 0; v < 4; v++) acc[i][j][v] = 0.f;

    auto load_stage = [&](int st, int k0) {
        const uint32_t sa = sb + st * STG_SZ;
        const uint32_t sbm = sa + 16384;
        #pragma unroll
        for (int i = 0; i < 4; i++) {
            int id = i * 256 + tid;
            int row = id >> 3, c = id & 7;
            uint32_t off = (uint32_t)row * 128 + (uint32_t)((c ^ (row & 7)) << 4);
            cpasync16(sa + off, Ag + (long)(m0 + row) * NN + k0 + c * 8);
            cpasync16(sbm + off, Bg + (long)(n0 + row) * NN + k0 + c * 8);
        }
        cpasync_commit();
    };

    #pragma unroll
    for (int s = 0; s < STAGES - 1; s++) load_stage(s, s * 64);

    int cs = 0, ns = STAGES - 1;     // compute-stage, next-load-stage indices
    for (int kt = 0; kt < KT; kt++) {
        if (kt < KT - 1) cpasync_wait<STAGES - 2>();
        else             cpasync_wait<0>();
        __syncthreads();
        const int kn = kt + STAGES - 1;
        if (kn < KT) {
            load_stage(ns, kn * 64);
            if (++ns == STAGES) ns = 0;
        }

        const uint32_t sa = sb + cs * STG_SZ;
        const uint32_t sbm = sa + 16384;
        if (++cs == STAGES) cs = 0;
        #pragma unroll
        for (int kk = 0; kk < 4; kk++) {
            uint32_t a[4][4], b[4][2];
            #pragma unroll
            for (int mi = 0; mi < 4; mi++) {
                int row = wm + mi * 16 + (lane & 15);
                int c = kk * 2 + (lane >> 4);
                ldmx4(a[mi], sa + row * 128 + ((c ^ (row & 7)) << 4));
            }
            #pragma unroll
            for (int ni = 0; ni < 4; ni++) {
                int row = wn + ni * 8 + (lane & 7);
                int c = kk * 2 + ((lane >> 3) & 1);
                ldmx2(b[ni], sbm + row * 128 + ((c ^ (row & 7)) << 4));
            }
            #pragma unroll
            for (int mi = 0; mi < 4; mi++)
                #pragma unroll
                for (int ni = 0; ni < 4; ni++)
                    mma16(acc[mi][ni], a[mi], b[ni]);
        }
        __syncthreads();
    }

    #pragma unroll
    for (int mi = 0; mi < 4; mi++) {
        #pragma unroll
        for (int ni = 0; ni < 4; ni++) {
            int r0 = m0 + wm + mi * 16 + (lane >> 2);
            int c0 = n0 + wn + ni * 8 + (lane & 3) * 2;
            float2 v0; v0.x = acc[mi][ni][0]; v0.y = acc[mi][ni][1];
            float2 v1; v1.x = acc[mi][ni][2]; v1.y = acc[mi][ni][3];
            *(float2*)&C[(long)r0 * ldc + c0]       = v0;
            *(float2*)&C[(long)(r0 + 8) * ldc + c0] = v1;
        }
    }
}

// ---------------- softmax over relations ----------------
__global__ void softmax_k(const float* __restrict__ W) {
    int t = threadIdx.x;
    if (t < 6) {
        const float* w = W + t * RR;
        float mx = w[0];
        #pragma unroll
        for (int r = 1; r < RR; r++) mx = fmaxf(mx, w[r]);
        float e[RR], s = 0.f;
        #pragma unroll
        for (int r = 0; r < RR; r++) { e[r] = expf(w[r] - mx); s += e[r]; }
        #pragma unroll
        for (int r = 0; r < RR; r++) g_F[t * RR + r] = e[r] / s;
    }
}

// ------- fused qcombine + transpose: one A read -> Q0 straight, Q1t/Q2t transposed
__global__ __launch_bounds__(256) void qcombine_t_k(const float* __restrict__ A) {
    __shared__ float t[RR][32][33];
    const int x0 = blockIdx.x * 32, y0 = blockIdx.y * 32;   // x: m (cols), y: n (rows)
    const int tx = threadIdx.x & 31, ty = threadIdx.x >> 5; // 32 x 8
    #pragma unroll
    for (int r = 0; r < RR; r++)
        #pragma unroll
        for (int i = 0; i < 4; i++)
            t[r][ty + 8 * i][tx] = A[(long)r * NN * NN + (long)(y0 + ty + 8 * i) * NN + x0 + tx];
    __syncthreads();

    float f[6][RR];
    #pragma unroll
    for (int c = 0; c < 6; c++)
        #pragma unroll
        for (int r = 0; r < RR; r++) f[c][r] = g_F[c * RR + r];

    // straight: Q0 channel 0/1  -> out[n][m]
    #pragma unroll
    for (int c = 0; c < 2; c++)
        #pragma unroll
        for (int i = 0; i < 4; i++) {
            int row = ty + 8 * i;
            float v = 0.f;
            #pragma unroll
            for (int r = 0; r < RR; r++) v = fmaf(f[c][r], t[r][row][tx], v);
            g_Q0f[(long)c * NN * NN + (long)(y0 + row) * NN + x0 + tx] = __float2half_rn(v);
        }
    // transposed: Q1t (c=2,3), Q2t (c=4,5) -> out[m][n] = val[n][m]
    #pragma unroll
    for (int c = 2; c < 6; c++) {
        __half* dst = (c < 4 ? g_Q1t : g_Q2t) + (long)(c & 1) * NN * NN;
        #pragma unroll
        for (int i = 0; i < 4; i++) {
            int rr = ty + 8 * i;                 // local m
            float v = 0.f;
            #pragma unroll
            for (int r = 0; r < RR; r++) v = fmaf(f[c][r], t[r][tx][rr], v);
            dst[(long)(x0 + rr) * NN + y0 + tx] = __float2half_rn(v);
        }
    }
}

// ---------------- h transpose: h[n][d] fp32 -> hT[d][n] fp16 ----------------
__global__ __launch_bounds__(256) void htrans_k(const float* __restrict__ h) {
    __shared__ float t[32][33];
    const int x0 = blockIdx.x * 32, y0 = blockIdx.y * 32;   // x: d, y: n
    const int tx = threadIdx.x & 31, ty = threadIdx.x >> 5;
    #pragma unroll
    for (int i = 0; i < 4; i++)
        t[ty + 8 * i][tx] = h[(long)(y0 + ty + 8 * i) * DD + x0 + tx];
    __syncthreads();
    #pragma unroll
    for (int i = 0; i < 4; i++) {
        int rr = ty + 8 * i;
        g_hT[(long)(x0 + rr) * NN + y0 + tx] = __float2half_rn(t[tx][rr]);
    }
}

// ---------------- SIMT SGEMM (gcn tail only) ----------------
template<bool TA, bool EPI>
__global__ __launch_bounds__(256) void sgemm_k(
    const float* __restrict__ A, const float* __restrict__ B,
    float* __restrict__ C, const float* __restrict__ bias,
    int M, int N, int K, long sA, long sB, long sC)
{
    constexpr int BM = 128, BN = 128, BK = 8;
    __shared__ float As[BK][BM];
    __shared__ float Bs[BK][BN];
    A += (long)blockIdx.z * sA;
    B += (long)blockIdx.z * sB;
    C += (long)blockIdx.z * sC;
    const int bm = blockIdx.y * BM, bn = blockIdx.x * BN;
    const int tid = threadIdx.x;
    const int tx = tid & 15, ty = tid >> 4;

    float acc[8][8];
    #pragma unroll
    for (int i = 0; i < 8; i++)
        #pragma unroll
        for (int j = 0; j < 8; j++) acc[i][j] = 0.f;

    for (int k0 = 0; k0 < K; k0 += BK) {
        if (!TA) {
            int row = tid >> 1;
            int col = (tid & 1) * 4;
            float4 v = *(const float4*)&A[(long)(bm + row) * K + k0 + col];
            As[col + 0][row] = v.x; As[col + 1][row] = v.y;
            As[col + 2][row] = v.z; As[col + 3][row] = v.w;
        } else {
            int kk = tid >> 5;
            int mm = (tid & 31) * 4;
            *(float4*)&As[kk][mm] = *(const float4*)&A[(long)(k0 + kk) * M + bm + mm];
        }
        {
            int kk = tid >> 5;
            int nn = (tid & 31) * 4;
            *(float4*)&Bs[kk][nn] = *(const float4*)&B[(long)(k0 + kk) * N + bn + nn];
        }
        __syncthreads();
        #pragma unroll
        for (int kk = 0; kk < BK; kk++) {
            float a[8], b[8];
            #pragma unroll
            for (int i = 0; i < 8; i++) a[i] = As[kk][ty * 8 + i];
            #pragma unroll
            for (int j = 0; j < 8; j++) b[j] = Bs[kk][tx * 8 + j];
            #pragma unroll
            for (int i = 0; i < 8; i++)
                #pragma unroll
                for (int j = 0; j < 8; j++)
                    acc[i][j] = fmaf(a[i], b[j], acc[i][j]);
        }
        __syncthreads();
    }

    #pragma unroll
    for (int i = 0; i < 8; i++) {
        long r = bm + ty * 8 + i;
        float* Crow = C + r * (long)N + bn + tx * 8;
        #pragma unroll
        for (int j = 0; j < 8; j += 4) {
            float4 v;
            float v0 = acc[i][j], v1 = acc[i][j + 1], v2 = acc[i][j + 2], v3 = acc[i][j + 3];
            if (EPI) {
                const float* bp = bias + bn + tx * 8 + j;
                v0 = fmaxf(v0 + bp[0], 0.f);
                v1 = fmaxf(v1 + bp[1], 0.f);
                v2 = fmaxf(v2 + bp[2], 0.f);
                v3 = fmaxf(v3 + bp[3], 0.f);
            }
            v.x = v0; v.y = v1; v.z = v2; v.w = v3;
            *(float4*)&Crow[j] = v;
        }
    }
}

// ---------------- column sums ----------------
__global__ __launch_bounds__(128) void colsum_part_k(const float* __restrict__ H) {
    int cg = blockIdx.x, jc = blockIdx.y;
    int col = cg * 128 + threadIdx.x;
    int c = col / NN, m = col % NN;
    const float* Hc = H + (long)c * NN * NN;
    float s = 0.f;
    int n0 = jc * 128;
    #pragma unroll 4
    for (int n = n0; n < n0 + 128; n++)
        s += Hc[(long)n * NN + m];
    g_part[(long)c * 16 * NN + (long)jc * NN + m] = s;
}
__global__ __launch_bounds__(128) void colsum_final_k(const float* __restrict__ H) {
    int idx = blockIdx.x * blockDim.x + threadIdx.x;
    if (idx >= CC * NN) return;
    int c = idx / NN, m = idx % NN;
    float s = 0.f;
    #pragma unroll
    for (int j = 0; j < 16; j++)
        s += g_part[(long)c * 16 * NN + (long)j * NN + m];
    s -= H[(long)c * NN * NN + (long)m * NN + m];
    g_deg[idx] = s;
}

// ---------------- mid norm -> fp16 A operand of GEMM2 ----------------
__global__ __launch_bounds__(256) void norm_mid_k(const float* __restrict__ H) {
    long i = (long)blockIdx.x * blockDim.x + threadIdx.x;
    if (i >= (long)CC * NN * NN) return;
    int c = (int)(i / ((long)NN * NN));
    long rem = i % ((long)NN * NN);
    int n = (int)(rem / NN), m = (int)(rem % NN);
    float d = g_deg[c * NN + m];
    float v = (n == m || d <= 0.f) ? 0.f : H[i] / d;
    g_Hf[i] = __float2half_rn(v);
}

// ------- final double normalization fused with transpose -> fp16 HsT[m][n] ----
__global__ __launch_bounds__(256) void norm_final_t_k(const float* __restrict__ H) {
    __shared__ float t[32][33];
    const int c = blockIdx.z;
    const int x0 = blockIdx.x * 32, y0 = blockIdx.y * 32;   // x: m (col), y: n (row)
    const int tx = threadIdx.x & 31, ty = threadIdx.x >> 5;
    const float d1 = g_deg[c * NN + x0 + tx];
    const float inv1 = (d1 > 0.f) ? 1.f / d1 : 0.f;
    const float inv2 = (d1 > 0.f) ? 0.5f : 1.f;
    const float* Hc = H + (long)c * NN * NN;
    #pragma unroll
    for (int i = 0; i < 4; i++) {
        int n = y0 + ty + 8 * i, m = x0 + tx;
        float v = Hc[(long)n * NN + m];
        v = (n == m) ? 1.f : v * inv1;
        t[ty + 8 * i][tx] = v * inv2;
    }
    __syncthreads();
    __half* dst = g_HsT + (long)c * NN * NN;
    #pragma unroll
    for (int i = 0; i < 4; i++) {
        int rr = ty + 8 * i;
        dst[(long)(x0 + rr) * NN + y0 + tx] = __float2half_rn(t[tx][rr]);
    }
}

// ---------------- lin1 / lin2 ----------------
__global__ __launch_bounds__(128) void lin1_k(const float* __restrict__ w,
                                              const float* __restrict__ b) {
    __shared__ float xr[CC * HD];
    int m = blockIdx.x, t = threadIdx.x;
    xr[t]      = g_X[(long)m * HD + t];
    xr[HD + t] = g_X[(long)NN * HD + (long)m * HD + t];
    __syncthreads();
    float acc = b[t];
    #pragma unroll 8
    for (int k = 0; k < CC * HD; k++)
        acc = fmaf(xr[k], w[k * HD + t], acc);
    g_X2[(long)m * HD + t] = fmaxf(acc, 0.f);
}
__global__ __launch_bounds__(128) void lin2_k(const int* __restrict__ idx,
                                              const float* __restrict__ w,
                                              const float* __restrict__ b,
                                              float* __restrict__ y, int ncat) {
    int i = blockIdx.x * blockDim.x + threadIdx.x;
    if (i >= ncat * NCLS) return;
    int row = i / NCLS, j = i % NCLS;
    const float* x = g_X2 + (long)idx[row] * HD;
    float acc = b[j];
    #pragma unroll 8
    for (int k = 0; k < HD; k++)
        acc = fmaf(x[k], w[k * NCLS + j], acc);
    y[i] = acc;
}

// ---------------- launch ----------------
extern "C" void kernel_launch(void* const* d_in, const int* in_sizes, int n_in,
                              void* d_out, int out_size) {
    const float *A = 0, *h = 0, *W_conv = 0, *gcn_w = 0, *gcn_b = 0;
    const float *lin1_w = 0, *lin1_b = 0, *lin2_w = 0, *lin2_b = 0;
    const int* catidx = 0;
    int ncat = 0;
    for (int i = 0; i < n_in; i++) {
        int s = in_sizes[i];
        const void* p = d_in[i];
        if      (s == RR * NN * NN) A = (const float*)p;
        else if (s == NN * DD)      h = (const float*)p;
        else if (s == 3 * CC * RR)  W_conv = (const float*)p;
        else if (s == DD * HD) { if (!gcn_w) gcn_w = (const float*)p; else lin1_w = (const float*)p; }
        else if (s == HD)      { if (!gcn_b) gcn_b = (const float*)p; else lin1_b = (const float*)p; }
        else if (s == HD * NCLS) lin2_w = (const float*)p;
        else if (s == NCLS)      lin2_b = (const float*)p;
        else { catidx = (const int*)p; ncat = s; }
    }
    float* y = (float*)d_out;

    float *H, *H2, *agg, *X;
    __half *Q0f, *Q1t, *Q2t, *Hf, *HsT, *hT;
    cudaGetSymbolAddress((void**)&H,   g_H);
    cudaGetSymbolAddress((void**)&H2,  g_H2);
    cudaGetSymbolAddress((void**)&agg, g_agg);
    cudaGetSymbolAddress((void**)&X,   g_X);
    cudaGetSymbolAddress((void**)&Q0f, g_Q0f);
    cudaGetSymbolAddress((void**)&Q1t, g_Q1t);
    cudaGetSymbolAddress((void**)&Q2t, g_Q2t);
    cudaGetSymbolAddress((void**)&Hf,  g_Hf);
    cudaGetSymbolAddress((void**)&HsT, g_HsT);
    cudaGetSymbolAddress((void**)&hT,  g_hT);

    static int smem_set = 0;
    if (!smem_set) {
        cudaFuncSetAttribute(gemm16_k, cudaFuncAttributeMaxDynamicSharedMemorySize, SMEM16);
        smem_set = 1;
    }

    const long NNNN = (long)NN * NN;

    softmax_k<<<1, 32>>>(W_conv);
    qcombine_t_k<<<dim3(NN / 32, NN / 32), 256>>>(A);
    htrans_k<<<dim3(DD / 32, NN / 32), 256>>>(h);

    // GEMM1: H = Q0 @ Q1^T
    gemm16_k<<<dim3(16, 16, CC), 256, SMEM16>>>(Q0f, Q1t, H, NN, NNNN, NNNN, NNNN);

    colsum_part_k<<<dim3(CC * NN / 128, 16), 128>>>(H);
    colsum_final_k<<<CC * NN / 128, 128>>>(H);
    norm_mid_k<<<(int)(CC * NNNN / 256), 256>>>(H);

    // GEMM2: H2 = Hn @ Q2^T
    gemm16_k<<<dim3(16, 16, CC), 256, SMEM16>>>(Hf, Q2t, H2, NN, NNNN, NNNN, NNNN);

    colsum_part_k<<<dim3(CC * NN / 128, 16), 128>>>(H2);
    colsum_final_k<<<CC * NN / 128, 128>>>(H2);
    norm_final_t_k<<<dim3(NN / 32, NN / 32, CC), 256>>>(H2);

    // AGG: agg[c][m][d] = sum_n HsT[c][m][n] * hT[d][n]   (tensor cores)
    gemm16_k<<<dim3(DD / 128, NN / 128, CC), 256, SMEM16>>>(HsT, hT, agg,
                                                            DD, NNNN, 0, (long)NN * DD);

    // X = relu(agg @ gcn_w + gcn_b)
    {
        dim3 g(HD / 128, NN / 128, CC);
        sgemm_k<false, true><<<g, 256>>>(agg, gcn_w, X, gcn_b,
                                         NN, HD, DD, (long)NN * DD, 0, (long)NN * HD);
    }
    lin1_k<<<NN, 128>>>(lin1_w, lin1_b);
    lin2_k<<<(ncat * NCLS + 127) / 128, 128>>>(catidx, lin2_w, lin2_b, y, ncat);
}

// round 10
// speedup vs baseline: 2.1509x; 1.1400x over previous
#include <cuda_runtime.h>
#include <cuda_fp16.h>
#include <math.h>
#include <stdint.h>

#define NN   2048
#define RR   5
#define CC   2
#define DD   256
#define HD   128
#define NCLS 16
#define KS   4          // split-K factor for agg

// ---------------- scratch (device globals, no allocations) ----------------
__device__ float g_F[6 * RR];
__device__ float g_H [CC * NN * NN];
__device__ float g_H2[CC * NN * NN];
__device__ float g_part[CC * 16 * NN];
__device__ float g_deg [CC * NN];
__device__ float g_agg[CC * NN * DD];
__device__ float g_aggp[KS * CC * NN * DD];
__device__ float g_X  [CC * NN * HD];
__device__ float g_X2 [NN * HD];
__device__ __half g_Q0f[CC * NN * NN];
__device__ __half g_Q1t[CC * NN * NN];
__device__ __half g_Q2t[CC * NN * NN];
__device__ __half g_Hf [CC * NN * NN];
__device__ __half g_HsT[CC * NN * NN];
__device__ __half g_hT [DD * NN];

// ================= PTX helpers =================
__device__ __forceinline__ uint32_t smem_u32(const void* p) {
    uint32_t a;
    asm("{ .reg .u64 t; cvta.to.shared.u64 t, %1; cvt.u32.u64 %0, t; }" : "=r"(a) : "l"(p));
    return a;
}
__device__ __forceinline__ void cpasync16(uint32_t dst, const void* src) {
    asm volatile("cp.async.cg.shared.global [%0], [%1], 16;" :: "r"(dst), "l"(src) : "memory");
}
__device__ __forceinline__ void cpasync_commit() {
    asm volatile("cp.async.commit_group;" ::: "memory");
}
template<int N> __device__ __forceinline__ void cpasync_wait() {
    asm volatile("cp.async.wait_group %0;" :: "n"(N) : "memory");
}
__device__ __forceinline__ void ldmx4(uint32_t* r, uint32_t a) {
    asm volatile("ldmatrix.sync.aligned.m8n8.x4.shared.b16 {%0,%1,%2,%3},[%4];"
        : "=r"(r[0]), "=r"(r[1]), "=r"(r[2]), "=r"(r[3]) : "r"(a));
}
__device__ __forceinline__ void mma16(float* c, const uint32_t* a, const uint32_t* b) {
    asm volatile("mma.sync.aligned.m16n8k16.row.col.f32.f16.f16.f32 "
        "{%0,%1,%2,%3},{%4,%5,%6,%7},{%8,%9},{%0,%1,%2,%3};"
        : "+f"(c[0]), "+f"(c[1]), "+f"(c[2]), "+f"(c[3])
        : "r"(a[0]), "r"(a[1]), "r"(a[2]), "r"(a[3]), "r"(b[0]), "r"(b[1]));
}

// ================= fp16 tensor-core GEMM =================
// C[M,N] = A[M,K] * B[N,K]^T, lda=ldb=NN. CTA tile 128x128, 4 warps (64x64 each),
// BK=64, 3-stage cp.async. Optional fused per-tile column sums -> g_part.
#define STAGES  3
#define STG_SZ  32768
#define SMEM16  (STAGES * STG_SZ)

template<bool COLSUM>
__global__ __launch_bounds__(128, 2) void gemm16_k(
    const __half* __restrict__ Ag, const __half* __restrict__ Bg,
    float* __restrict__ C, int ldc, long sA, long sB, long sC,
    int cmod, int ktn)
{
    extern __shared__ char smem[];
    const uint32_t sb = smem_u32(smem);
    const int tid = threadIdx.x, lane = tid & 31, warp = tid >> 5;
    const int m0 = blockIdx.y * 128, n0 = blockIdx.x * 128;
    const int z = blockIdx.z;
    const int c = cmod ? (z % cmod) : z;
    const int kt0 = cmod ? (z / cmod) * ktn : 0;
    Ag += (long)c * sA;
    Bg += (long)c * sB;
    C  += (long)z * sC;
    const int wm = (warp >> 1) * 64;
    const int wn = (warp & 1) * 64;

    float acc[4][8][4];
    #pragma unroll
    for (int i = 0; i < 4; i++)
        #pragma unroll
        for (int j = 0; j < 8; j++)
            #pragma unroll
            for (int v = 0; v < 4; v++) acc[i][j][v] = 0.f;

    auto load_stage = [&](int st, int k0) {
        const uint32_t sa = sb + st * STG_SZ;
        const uint32_t sbm = sa + 16384;
        #pragma unroll
        for (int i = 0; i < 8; i++) {
            int id = i * 128 + tid;              // 0..1023
            int row = id >> 3, cc = id & 7;
            uint32_t off = (uint32_t)row * 128 + (uint32_t)((cc ^ (row & 7)) << 4);
            cpasync16(sa + off, Ag + (long)(m0 + row) * NN + k0 + cc * 8);
            cpasync16(sbm + off, Bg + (long)(n0 + row) * NN + k0 + cc * 8);
        }
        cpasync_commit();
    };

    #pragma unroll
    for (int s = 0; s < STAGES - 1; s++) load_stage(s, (kt0 + s) * 64);

    int cs = 0, ns = STAGES - 1;
    for (int it = 0; it < ktn; it++) {
        if (it < ktn - 1) cpasync_wait<STAGES - 2>();
        else              cpasync_wait<0>();
        __syncthreads();
        const int kn = it + STAGES - 1;
        if (kn < ktn) {
            load_stage(ns, (kt0 + kn) * 64);
            if (++ns == STAGES) ns = 0;
        }

        const uint32_t sa = sb + cs * STG_SZ;
        const uint32_t sbm = sa + 16384;
        if (++cs == STAGES) cs = 0;
        #pragma unroll
        for (int kk = 0; kk < 4; kk++) {
            uint32_t a[4][4], b[4][4];
            #pragma unroll
            for (int mi = 0; mi < 4; mi++) {
                int row = wm + mi * 16 + (lane & 15);
                int cc = kk * 2 + (lane >> 4);
                ldmx4(a[mi], sa + row * 128 + ((cc ^ (row & 7)) << 4));
            }
            #pragma unroll
            for (int p = 0; p < 4; p++) {
                int row = wn + p * 16 + (lane & 7) + ((lane >> 4) << 3);
                int cc = kk * 2 + ((lane >> 3) & 1);
                ldmx4(b[p], sbm + row * 128 + ((cc ^ (row & 7)) << 4));
            }
            #pragma unroll
            for (int mi = 0; mi < 4; mi++)
                #pragma unroll
                for (int p = 0; p < 4; p++) {
                    mma16(acc[mi][p * 2],     a[mi], &b[p][0]);
                    mma16(acc[mi][p * 2 + 1], a[mi], &b[p][2]);
                }
        }
        __syncthreads();
    }

    // ---- store C ----
    #pragma unroll
    for (int mi = 0; mi < 4; mi++) {
        #pragma unroll
        for (int ni = 0; ni < 8; ni++) {
            int r0 = m0 + wm + mi * 16 + (lane >> 2);
            int c0 = n0 + wn + ni * 8 + (lane & 3) * 2;
            float2 v0; v0.x = acc[mi][ni][0]; v0.y = acc[mi][ni][1];
            float2 v1; v1.x = acc[mi][ni][2]; v1.y = acc[mi][ni][3];
            *(float2*)&C[(long)r0 * ldc + c0]       = v0;
            *(float2*)&C[(long)(r0 + 8) * ldc + c0] = v1;
        }
    }

    // ---- fused per-tile column sums (deterministic; tile partial -> g_part) ----
    if (COLSUM) {
        float* cs2 = (float*)smem;               // [2][128]
        __syncthreads();                         // done with stage smem
        #pragma unroll
        for (int ni = 0; ni < 8; ni++) {
            #pragma unroll
            for (int j = 0; j < 2; j++) {
                float s = 0.f;
                #pragma unroll
                for (int mi = 0; mi < 4; mi++)
                    s += acc[mi][ni][j] + acc[mi][ni][2 + j];
                s += __shfl_xor_sync(0xFFFFFFFF, s, 4);
                s += __shfl_xor_sync(0xFFFFFFFF, s, 8);
                s += __shfl_xor_sync(0xFFFFFFFF, s, 16);
                if (lane < 4)
                    cs2[(wm >> 6) * 128 + wn + ni * 8 + (lane & 3) * 2 + j] = s;
            }
        }
        __syncthreads();
        if (tid < 128) {
            float tot = cs2[tid] + cs2[128 + tid];
            g_part[(long)c * 16 * NN + (long)blockIdx.y * NN + n0 + tid] = tot;
        }
    }
}

// ---------------- softmax over relations ----------------
__global__ void softmax_k(const float* __restrict__ W) {
    int t = threadIdx.x;
    if (t < 6) {
        const float* w = W + t * RR;
        float mx = w[0];
        #pragma unroll
        for (int r = 1; r < RR; r++) mx = fmaxf(mx, w[r]);
        float e[RR], s = 0.f;
        #pragma unroll
        for (int r = 0; r < RR; r++) { e[r] = expf(w[r] - mx); s += e[r]; }
        #pragma unroll
        for (int r = 0; r < RR; r++) g_F[t * RR + r] = e[r] / s;
    }
}

// ------- fused qcombine + transpose ----------
__global__ __launch_bounds__(256) void qcombine_t_k(const float* __restrict__ A) {
    __shared__ float t[RR][32][33];
    const int x0 = blockIdx.x * 32, y0 = blockIdx.y * 32;
    const int tx = threadIdx.x & 31, ty = threadIdx.x >> 5;
    #pragma unroll
    for (int r = 0; r < RR; r++)
        #pragma unroll
        for (int i = 0; i < 4; i++)
            t[r][ty + 8 * i][tx] = A[(long)r * NN * NN + (long)(y0 + ty + 8 * i) * NN + x0 + tx];
    __syncthreads();

    float f[6][RR];
    #pragma unroll
    for (int c = 0; c < 6; c++)
        #pragma unroll
        for (int r = 0; r < RR; r++) f[c][r] = g_F[c * RR + r];

    #pragma unroll
    for (int c = 0; c < 2; c++)
        #pragma unroll
        for (int i = 0; i < 4; i++) {
            int row = ty + 8 * i;
            float v = 0.f;
            #pragma unroll
            for (int r = 0; r < RR; r++) v = fmaf(f[c][r], t[r][row][tx], v);
            g_Q0f[(long)c * NN * NN + (long)(y0 + row) * NN + x0 + tx] = __float2half_rn(v);
        }
    #pragma unroll
    for (int c = 2; c < 6; c++) {
        __half* dst = (c < 4 ? g_Q1t : g_Q2t) + (long)(c & 1) * NN * NN;
        #pragma unroll
        for (int i = 0; i < 4; i++) {
            int rr = ty + 8 * i;
            float v = 0.f;
            #pragma unroll
            for (int r = 0; r < RR; r++) v = fmaf(f[c][r], t[r][tx][rr], v);
            dst[(long)(x0 + rr) * NN + y0 + tx] = __float2half_rn(v);
        }
    }
}

// ---------------- h transpose ----------------
__global__ __launch_bounds__(256) void htrans_k(const float* __restrict__ h) {
    __shared__ float t[32][33];
    const int x0 = blockIdx.x * 32, y0 = blockIdx.y * 32;
    const int tx = threadIdx.x & 31, ty = threadIdx.x >> 5;
    #pragma unroll
    for (int i = 0; i < 4; i++)
        t[ty + 8 * i][tx] = h[(long)(y0 + ty + 8 * i) * DD + x0 + tx];
    __syncthreads();
    #pragma unroll
    for (int i = 0; i < 4; i++) {
        int rr = ty + 8 * i;
        g_hT[(long)(x0 + rr) * NN + y0 + tx] = __float2half_rn(t[tx][rr]);
    }
}

// ---------------- SIMT SGEMM (gcn tail) ----------------
template<bool EPI>
__global__ __launch_bounds__(256) void sgemm_k(
    const float* __restrict__ A, const float* __restrict__ B,
    float* __restrict__ C, const float* __restrict__ bias,
    int M, int N, int K, long sA, long sB, long sC)
{
    constexpr int BM = 128, BN = 128, BK = 8;
    __shared__ float As[BK][BM];
    __shared__ float Bs[BK][BN];
    A += (long)blockIdx.z * sA;
    B += (long)blockIdx.z * sB;
    C += (long)blockIdx.z * sC;
    const int bm = blockIdx.y * BM, bn = blockIdx.x * BN;
    const int tid = threadIdx.x;
    const int tx = tid & 15, ty = tid >> 4;

    float acc[8][8];
    #pragma unroll
    for (int i = 0; i < 8; i++)
        #pragma unroll
        for (int j = 0; j < 8; j++) acc[i][j] = 0.f;

    for (int k0 = 0; k0 < K; k0 += BK) {
        {
            int row = tid >> 1;
            int col = (tid & 1) * 4;
            float4 v = *(const float4*)&A[(long)(bm + row) * K + k0 + col];
            As[col + 0][row] = v.x; As[col + 1][row] = v.y;
            As[col + 2][row] = v.z; As[col + 3][row] = v.w;
        }
        {
            int kk = tid >> 5;
            int nn = (tid & 31) * 4;
            *(float4*)&Bs[kk][nn] = *(const float4*)&B[(long)(k0 + kk) * N + bn + nn];
        }
        __syncthreads();
        #pragma unroll
        for (int kk = 0; kk < BK; kk++) {
            float a[8], b[8];
            #pragma unroll
            for (int i = 0; i < 8; i++) a[i] = As[kk][ty * 8 + i];
            #pragma unroll
            for (int j = 0; j < 8; j++) b[j] = Bs[kk][tx * 8 + j];
            #pragma unroll
            for (int i = 0; i < 8; i++)
                #pragma unroll
                for (int j = 0; j < 8; j++)
                    acc[i][j] = fmaf(a[i], b[j], acc[i][j]);
        }
        __syncthreads();
    }

    #pragma unroll
    for (int i = 0; i < 8; i++) {
        long r = bm + ty * 8 + i;
        float* Crow = C + r * (long)N + bn + tx * 8;
        #pragma unroll
        for (int j = 0; j < 8; j += 4) {
            float4 v;
            float v0 = acc[i][j], v1 = acc[i][j + 1], v2 = acc[i][j + 2], v3 = acc[i][j + 3];
            if (EPI) {
                const float* bp = bias + bn + tx * 8 + j;
                v0 = fmaxf(v0 + bp[0], 0.f);
                v1 = fmaxf(v1 + bp[1], 0.f);
                v2 = fmaxf(v2 + bp[2], 0.f);
                v3 = fmaxf(v3 + bp[3], 0.f);
            }
            v.x = v0; v.y = v1; v.z = v2; v.w = v3;
            *(float4*)&Crow[j] = v;
        }
    }
}

// ---------------- colsum final (g_part -> g_deg) ----------------
__global__ __launch_bounds__(128) void colsum_final_k(const float* __restrict__ H) {
    int idx = blockIdx.x * blockDim.x + threadIdx.x;
    if (idx >= CC * NN) return;
    int c = idx / NN, m = idx % NN;
    float s = 0.f;
    #pragma unroll
    for (int j = 0; j < 16; j++)
        s += g_part[(long)c * 16 * NN + (long)j * NN + m];
    s -= H[(long)c * NN * NN + (long)m * NN + m];
    g_deg[idx] = s;
}

// ---------------- mid norm -> fp16 ----------------
__global__ __launch_bounds__(256) void norm_mid_k(const float* __restrict__ H) {
    long i = (long)blockIdx.x * blockDim.x + threadIdx.x;
    if (i >= (long)CC * NN * NN) return;
    int c = (int)(i / ((long)NN * NN));
    long rem = i % ((long)NN * NN);
    int n = (int)(rem / NN), m = (int)(rem % NN);
    float d = g_deg[c * NN + m];
    float v = (n == m || d <= 0.f) ? 0.f : H[i] / d;
    g_Hf[i] = __float2half_rn(v);
}

// ------- final double norm fused with transpose -> fp16 HsT ----
__global__ __launch_bounds__(256) void norm_final_t_k(const float* __restrict__ H) {
    __shared__ float t[32][33];
    const int c = blockIdx.z;
    const int x0 = blockIdx.x * 32, y0 = blockIdx.y * 32;
    const int tx = threadIdx.x & 31, ty = threadIdx.x >> 5;
    const float d1 = g_deg[c * NN + x0 + tx];
    const float inv1 = (d1 > 0.f) ? 1.f / d1 : 0.f;
    const float inv2 = (d1 > 0.f) ? 0.5f : 1.f;
    const float* Hc = H + (long)c * NN * NN;
    #pragma unroll
    for (int i = 0; i < 4; i++) {
        int n = y0 + ty + 8 * i, m = x0 + tx;
        float v = Hc[(long)n * NN + m];
        v = (n == m) ? 1.f : v * inv1;
        t[ty + 8 * i][tx] = v * inv2;
    }
    __syncthreads();
    __half* dst = g_HsT + (long)c * NN * NN;
    #pragma unroll
    for (int i = 0; i < 4; i++) {
        int rr = ty + 8 * i;
        dst[(long)(x0 + rr) * NN + y0 + tx] = __float2half_rn(t[tx][rr]);
    }
}

// ---------------- split-K reduce for agg ----------------
__global__ __launch_bounds__(256) void aggreduce_k() {
    long i4 = ((long)blockIdx.x * blockDim.x + threadIdx.x) * 4;
    if (i4 >= (long)CC * NN * DD) return;
    float4 s = *(const float4*)&g_aggp[i4];
    #pragma unroll
    for (int ks = 1; ks < KS; ks++) {
        const float4 v = *(const float4*)&g_aggp[(long)ks * CC * NN * DD + i4];
        s.x += v.x; s.y += v.y; s.z += v.z; s.w += v.w;
    }
    *(float4*)&g_agg[i4] = s;
}

// ---------------- lin1 / lin2 ----------------
__global__ __launch_bounds__(128) void lin1_k(const float* __restrict__ w,
                                              const float* __restrict__ b) {
    __shared__ float xr[CC * HD];
    int m = blockIdx.x, t = threadIdx.x;
    xr[t]      = g_X[(long)m * HD + t];
    xr[HD + t] = g_X[(long)NN * HD + (long)m * HD + t];
    __syncthreads();
    float acc = b[t];
    #pragma unroll 8
    for (int k = 0; k < CC * HD; k++)
        acc = fmaf(xr[k], w[k * HD + t], acc);
    g_X2[(long)m * HD + t] = fmaxf(acc, 0.f);
}
__global__ __launch_bounds__(128) void lin2_k(const int* __restrict__ idx,
                                              const float* __restrict__ w,
                                              const float* __restrict__ b,
                                              float* __restrict__ y, int ncat) {
    int i = blockIdx.x * blockDim.x + threadIdx.x;
    if (i >= ncat * NCLS) return;
    int row = i / NCLS, j = i % NCLS;
    const float* x = g_X2 + (long)idx[row] * HD;
    float acc = b[j];
    #pragma unroll 8
    for (int k = 0; k < HD; k++)
        acc = fmaf(x[k], w[k * NCLS + j], acc);
    y[i] = acc;
}

// ---------------- launch ----------------
extern "C" void kernel_launch(void* const* d_in, const int* in_sizes, int n_in,
                              void* d_out, int out_size) {
    const float *A = 0, *h = 0, *W_conv = 0, *gcn_w = 0, *gcn_b = 0;
    const float *lin1_w = 0, *lin1_b = 0, *lin2_w = 0, *lin2_b = 0;
    const int* catidx = 0;
    int ncat = 0;
    for (int i = 0; i < n_in; i++) {
        int s = in_sizes[i];
        const void* p = d_in[i];
        if      (s == RR * NN * NN) A = (const float*)p;
        else if (s == NN * DD)      h = (const float*)p;
        else if (s == 3 * CC * RR)  W_conv = (const float*)p;
        else if (s == DD * HD) { if (!gcn_w) gcn_w = (const float*)p; else lin1_w = (const float*)p; }
        else if (s == HD)      { if (!gcn_b) gcn_b = (const float*)p; else lin1_b = (const float*)p; }
        else if (s == HD * NCLS) lin2_w = (const float*)p;
        else if (s == NCLS)      lin2_b = (const float*)p;
        else { catidx = (const int*)p; ncat = s; }
    }
    float* y = (float*)d_out;

    float *H, *H2, *agg, *aggp, *X;
    __half *Q0f, *Q1t, *Q2t, *Hf, *HsT, *hT;
    cudaGetSymbolAddress((void**)&H,    g_H);
    cudaGetSymbolAddress((void**)&H2,   g_H2);
    cudaGetSymbolAddress((void**)&agg,  g_agg);
    cudaGetSymbolAddress((void**)&aggp, g_aggp);
    cudaGetSymbolAddress((void**)&X,    g_X);
    cudaGetSymbolAddress((void**)&Q0f,  g_Q0f);
    cudaGetSymbolAddress((void**)&Q1t,  g_Q1t);
    cudaGetSymbolAddress((void**)&Q2t,  g_Q2t);
    cudaGetSymbolAddress((void**)&Hf,   g_Hf);
    cudaGetSymbolAddress((void**)&HsT,  g_HsT);
    cudaGetSymbolAddress((void**)&hT,   g_hT);

    static int smem_set = 0;
    if (!smem_set) {
        cudaFuncSetAttribute(gemm16_k<true>,  cudaFuncAttributeMaxDynamicSharedMemorySize, SMEM16);
        cudaFuncSetAttribute(gemm16_k<false>, cudaFuncAttributeMaxDynamicSharedMemorySize, SMEM16);
        smem_set = 1;
    }

    const long NNNN = (long)NN * NN;

    softmax_k<<<1, 32>>>(W_conv);
    qcombine_t_k<<<dim3(NN / 32, NN / 32), 256>>>(A);
    htrans_k<<<dim3(DD / 32, NN / 32), 256>>>(h);

    // GEMM1: H = Q0 @ Q1^T  (+ fused tile column sums)
    gemm16_k<true><<<dim3(16, 16, CC), 128, SMEM16>>>(Q0f, Q1t, H, NN,
                                                      NNNN, NNNN, NNNN, 0, 32);
    colsum_final_k<<<CC * NN / 128, 128>>>(H);
    norm_mid_k<<<(int)(CC * NNNN / 256), 256>>>(H);

    // GEMM2: H2 = Hn @ Q2^T  (+ fused tile column sums)
    gemm16_k<true><<<dim3(16, 16, CC), 128, SMEM16>>>(Hf, Q2t, H2, NN,
                                                      NNNN, NNNN, NNNN, 0, 32);
    colsum_final_k<<<CC * NN / 128, 128>>>(H2);
    norm_final_t_k<<<dim3(NN / 32, NN / 32, CC), 256>>>(H2);

    // AGG (split-K x4): aggp[ks*CC+c] = HsT[c] @ hT^T over K-slice
    gemm16_k<false><<<dim3(DD / 128, NN / 128, CC * KS), 128, SMEM16>>>(
        HsT, hT, aggp, DD, NNNN, 0, (long)NN * DD, CC, 32 / KS);
    aggreduce_k<<<(int)(CC * NN * DD / 4 / 256), 256>>>();

    // X = relu(agg @ gcn_w + gcn_b)
    {
        dim3 g(HD / 128, NN / 128, CC);
        sgemm_k<true><<<g, 256>>>(agg, gcn_w, X, gcn_b,
                                  NN, HD, DD, (long)NN * DD, 0, (long)NN * HD);
    }
    lin1_k<<<NN, 128>>>(lin1_w, lin1_b);
    lin2_k<<<(ncat * NCLS + 127) / 128, 128>>>(catidx, lin2_w, lin2_b, y, ncat);
}

// round 11
// speedup vs baseline: 2.1515x; 1.0003x over previous
#include <cuda_runtime.h>
#include <cuda_fp16.h>
#include <math.h>
#include <stdint.h>

#define NN   2048
#define RR   5
#define CC   2
#define DD   256
#define HD   128
#define NCLS 16
#define KS   4          // split-K factor for agg

// ---------------- scratch (device globals, no allocations) ----------------
__device__ float g_F[6 * RR];
__device__ float g_H [CC * NN * NN];
__device__ float g_H2[CC * NN * NN];
__device__ float g_part[CC * 16 * NN];
__device__ float g_deg [CC * NN];
__device__ float g_agg[CC * NN * DD];
__device__ float g_aggp[KS * CC * NN * DD];
__device__ float g_X  [CC * NN * HD];
__device__ float g_X2 [NN * HD];
__device__ __half g_Q0f[CC * NN * NN];
__device__ __half g_Q1t[CC * NN * NN];
__device__ __half g_Q2t[CC * NN * NN];
__device__ __half g_Hf [CC * NN * NN];
__device__ __half g_HsT[CC * NN * NN];
__device__ __half g_hT [DD * NN];

// ================= PTX helpers =================
__device__ __forceinline__ uint32_t smem_u32(const void* p) {
    uint32_t a;
    asm("{ .reg .u64 t; cvta.to.shared.u64 t, %1; cvt.u32.u64 %0, t; }" : "=r"(a) : "l"(p));
    return a;
}
__device__ __forceinline__ void cpasync16(uint32_t dst, const void* src) {
    asm volatile("cp.async.cg.shared.global [%0], [%1], 16;" :: "r"(dst), "l"(src) : "memory");
}
__device__ __forceinline__ void cpasync_commit() {
    asm volatile("cp.async.commit_group;" ::: "memory");
}
template<int N> __device__ __forceinline__ void cpasync_wait() {
    asm volatile("cp.async.wait_group %0;" :: "n"(N) : "memory");
}
__device__ __forceinline__ void ldmx4(uint32_t* r, uint32_t a) {
    asm volatile("ldmatrix.sync.aligned.m8n8.x4.shared.b16 {%0,%1,%2,%3},[%4];"
        : "=r"(r[0]), "=r"(r[1]), "=r"(r[2]), "=r"(r[3]) : "r"(a));
}
__device__ __forceinline__ void mma16(float* c, const uint32_t* a, const uint32_t* b) {
    asm volatile("mma.sync.aligned.m16n8k16.row.col.f32.f16.f16.f32 "
        "{%0,%1,%2,%3},{%4,%5,%6,%7},{%8,%9},{%0,%1,%2,%3};"
        : "+f"(c[0]), "+f"(c[1]), "+f"(c[2]), "+f"(c[3])
        : "r"(a[0]), "r"(a[1]), "r"(a[2]), "r"(a[3]), "r"(b[0]), "r"(b[1]));
}

// ================= fp16 tensor-core GEMM =================
// C[M,N] = A[M,K] * B[N,K]^T, lda=ldb=NN. CTA tile 128x128, 4 warps (64x64 each),
// BK=64, 3-stage cp.async. Optional fused per-tile column sums -> g_part.
#define STAGES  3
#define STG_SZ  32768
#define SMEM16  (STAGES * STG_SZ)

template<bool COLSUM>
__global__ __launch_bounds__(128, 2) void gemm16_k(
    const __half* __restrict__ Ag, const __half* __restrict__ Bg,
    float* __restrict__ C, int ldc, long sA, long sB, long sC,
    int cmod, int ktn)
{
    extern __shared__ char smem[];
    const uint32_t sb = smem_u32(smem);
    const int tid = threadIdx.x, lane = tid & 31, warp = tid >> 5;
    const int m0 = blockIdx.y * 128, n0 = blockIdx.x * 128;
    const int z = blockIdx.z;
    const int c = cmod ? (z % cmod) : z;
    const int kt0 = cmod ? (z / cmod) * ktn : 0;
    Ag += (long)c * sA;
    Bg += (long)c * sB;
    C  += (long)z * sC;
    const int wm = (warp >> 1) * 64;
    const int wn = (warp & 1) * 64;

    float acc[4][8][4];
    #pragma unroll
    for (int i = 0; i < 4; i++)
        #pragma unroll
        for (int j = 0; j < 8; j++)
            #pragma unroll
            for (int v = 0; v < 4; v++) acc[i][j][v] = 0.f;

    auto load_stage = [&](int st, int k0) {
        const uint32_t sa = sb + st * STG_SZ;
        const uint32_t sbm = sa + 16384;
        #pragma unroll
        for (int i = 0; i < 8; i++) {
            int id = i * 128 + tid;              // 0..1023
            int row = id >> 3, cc = id & 7;
            uint32_t off = (uint32_t)row * 128 + (uint32_t)((cc ^ (row & 7)) << 4);
            cpasync16(sa + off, Ag + (long)(m0 + row) * NN + k0 + cc * 8);
            cpasync16(sbm + off, Bg + (long)(n0 + row) * NN + k0 + cc * 8);
        }
        cpasync_commit();
    };

    #pragma unroll
    for (int s = 0; s < STAGES - 1; s++) load_stage(s, (kt0 + s) * 64);

    int cs = 0, ns = STAGES - 1;
    for (int it = 0; it < ktn; it++) {
        if (it < ktn - 1) cpasync_wait<STAGES - 2>();
        else              cpasync_wait<0>();
        __syncthreads();
        const int kn = it + STAGES - 1;
        if (kn < ktn) {
            load_stage(ns, (kt0 + kn) * 64);
            if (++ns == STAGES) ns = 0;
        }

        const uint32_t sa = sb + cs * STG_SZ;
        const uint32_t sbm = sa + 16384;
        if (++cs == STAGES) cs = 0;
        #pragma unroll
        for (int kk = 0; kk < 4; kk++) {
            uint32_t a[4][4], b[4][4];
            #pragma unroll
            for (int mi = 0; mi < 4; mi++) {
                int row = wm + mi * 16 + (lane & 15);
                int cc = kk * 2 + (lane >> 4);
                ldmx4(a[mi], sa + row * 128 + ((cc ^ (row & 7)) << 4));
            }
            #pragma unroll
            for (int p = 0; p < 4; p++) {
                int row = wn + p * 16 + (lane & 7) + ((lane >> 4) << 3);
                int cc = kk * 2 + ((lane >> 3) & 1);
                ldmx4(b[p], sbm + row * 128 + ((cc ^ (row & 7)) << 4));
            }
            #pragma unroll
            for (int mi = 0; mi < 4; mi++)
                #pragma unroll
                for (int p = 0; p < 4; p++) {
                    mma16(acc[mi][p * 2],     a[mi], &b[p][0]);
                    mma16(acc[mi][p * 2 + 1], a[mi], &b[p][2]);
                }
        }
        __syncthreads();
    }

    // ---- store C ----
    #pragma unroll
    for (int mi = 0; mi < 4; mi++) {
        #pragma unroll
        for (int ni = 0; ni < 8; ni++) {
            int r0 = m0 + wm + mi * 16 + (lane >> 2);
            int c0 = n0 + wn + ni * 8 + (lane & 3) * 2;
            float2 v0; v0.x = acc[mi][ni][0]; v0.y = acc[mi][ni][1];
            float2 v1; v1.x = acc[mi][ni][2]; v1.y = acc[mi][ni][3];
            *(float2*)&C[(long)r0 * ldc + c0]       = v0;
            *(float2*)&C[(long)(r0 + 8) * ldc + c0] = v1;
        }
    }

    // ---- fused per-tile column sums (deterministic; tile partial -> g_part) ----
    if (COLSUM) {
        float* cs2 = (float*)smem;               // [2][128]
        __syncthreads();                         // done with stage smem
        #pragma unroll
        for (int ni = 0; ni < 8; ni++) {
            #pragma unroll
            for (int j = 0; j < 2; j++) {
                float s = 0.f;
                #pragma unroll
                for (int mi = 0; mi < 4; mi++)
                    s += acc[mi][ni][j] + acc[mi][ni][2 + j];
                s += __shfl_xor_sync(0xFFFFFFFF, s, 4);
                s += __shfl_xor_sync(0xFFFFFFFF, s, 8);
                s += __shfl_xor_sync(0xFFFFFFFF, s, 16);
                if (lane < 4)
                    cs2[(wm >> 6) * 128 + wn + ni * 8 + (lane & 3) * 2 + j] = s;
            }
        }
        __syncthreads();
        if (tid < 128) {
            float tot = cs2[tid] + cs2[128 + tid];
            g_part[(long)c * 16 * NN + (long)blockIdx.y * NN + n0 + tid] = tot;
        }
    }
}

// ---------------- softmax over relations ----------------
__global__ void softmax_k(const float* __restrict__ W) {
    int t = threadIdx.x;
    if (t < 6) {
        const float* w = W + t * RR;
        float mx = w[0];
        #pragma unroll
        for (int r = 1; r < RR; r++) mx = fmaxf(mx, w[r]);
        float e[RR], s = 0.f;
        #pragma unroll
        for (int r = 0; r < RR; r++) { e[r] = expf(w[r] - mx); s += e[r]; }
        #pragma unroll
        for (int r = 0; r < RR; r++) g_F[t * RR + r] = e[r] / s;
    }
}

// ------- fused qcombine + transpose ----------
__global__ __launch_bounds__(256) void qcombine_t_k(const float* __restrict__ A) {
    __shared__ float t[RR][32][33];
    const int x0 = blockIdx.x * 32, y0 = blockIdx.y * 32;
    const int tx = threadIdx.x & 31, ty = threadIdx.x >> 5;
    #pragma unroll
    for (int r = 0; r < RR; r++)
        #pragma unroll
        for (int i = 0; i < 4; i++)
            t[r][ty + 8 * i][tx] = A[(long)r * NN * NN + (long)(y0 + ty + 8 * i) * NN + x0 + tx];
    __syncthreads();

    float f[6][RR];
    #pragma unroll
    for (int c = 0; c < 6; c++)
        #pragma unroll
        for (int r = 0; r < RR; r++) f[c][r] = g_F[c * RR + r];

    #pragma unroll
    for (int c = 0; c < 2; c++)
        #pragma unroll
        for (int i = 0; i < 4; i++) {
            int row = ty + 8 * i;
            float v = 0.f;
            #pragma unroll
            for (int r = 0; r < RR; r++) v = fmaf(f[c][r], t[r][row][tx], v);
            g_Q0f[(long)c * NN * NN + (long)(y0 + row) * NN + x0 + tx] = __float2half_rn(v);
        }
    #pragma unroll
    for (int c = 2; c < 6; c++) {
        __half* dst = (c < 4 ? g_Q1t : g_Q2t) + (long)(c & 1) * NN * NN;
        #pragma unroll
        for (int i = 0; i < 4; i++) {
            int rr = ty + 8 * i;
            float v = 0.f;
            #pragma unroll
            for (int r = 0; r < RR; r++) v = fmaf(f[c][r], t[r][tx][rr], v);
            dst[(long)(x0 + rr) * NN + y0 + tx] = __float2half_rn(v);
        }
    }
}

// ---------------- h transpose ----------------
__global__ __launch_bounds__(256) void htrans_k(const float* __restrict__ h) {
    __shared__ float t[32][33];
    const int x0 = blockIdx.x * 32, y0 = blockIdx.y * 32;
    const int tx = threadIdx.x & 31, ty = threadIdx.x >> 5;
    #pragma unroll
    for (int i = 0; i < 4; i++)
        t[ty + 8 * i][tx] = h[(long)(y0 + ty + 8 * i) * DD + x0 + tx];
    __syncthreads();
    #pragma unroll
    for (int i = 0; i < 4; i++) {
        int rr = ty + 8 * i;
        g_hT[(long)(x0 + rr) * NN + y0 + tx] = __float2half_rn(t[tx][rr]);
    }
}

// ---------------- SIMT SGEMM (gcn tail) ----------------
template<bool EPI>
__global__ __launch_bounds__(256) void sgemm_k(
    const float* __restrict__ A, const float* __restrict__ B,
    float* __restrict__ C, const float* __restrict__ bias,
    int M, int N, int K, long sA, long sB, long sC)
{
    constexpr int BM = 128, BN = 128, BK = 8;
    __shared__ float As[BK][BM];
    __shared__ float Bs[BK][BN];
    A += (long)blockIdx.z * sA;
    B += (long)blockIdx.z * sB;
    C += (long)blockIdx.z * sC;
    const int bm = blockIdx.y * BM, bn = blockIdx.x * BN;
    const int tid = threadIdx.x;
    const int tx = tid & 15, ty = tid >> 4;

    float acc[8][8];
    #pragma unroll
    for (int i = 0; i < 8; i++)
        #pragma unroll
        for (int j = 0; j < 8; j++) acc[i][j] = 0.f;

    for (int k0 = 0; k0 < K; k0 += BK) {
        {
            int row = tid >> 1;
            int col = (tid & 1) * 4;
            float4 v = *(const float4*)&A[(long)(bm + row) * K + k0 + col];
            As[col + 0][row] = v.x; As[col + 1][row] = v.y;
            As[col + 2][row] = v.z; As[col + 3][row] = v.w;
        }
        {
            int kk = tid >> 5;
            int nn = (tid & 31) * 4;
            *(float4*)&Bs[kk][nn] = *(const float4*)&B[(long)(k0 + kk) * N + bn + nn];
        }
        __syncthreads();
        #pragma unroll
        for (int kk = 0; kk < BK; kk++) {
            float a[8], b[8];
            #pragma unroll
            for (int i = 0; i < 8; i++) a[i] = As[kk][ty * 8 + i];
            #pragma unroll
            for (int j = 0; j < 8; j++) b[j] = Bs[kk][tx * 8 + j];
            #pragma unroll
            for (int i = 0; i < 8; i++)
                #pragma unroll
                for (int j = 0; j < 8; j++)
                    acc[i][j] = fmaf(a[i], b[j], acc[i][j]);
        }
        __syncthreads();
    }

    #pragma unroll
    for (int i = 0; i < 8; i++) {
        long r = bm + ty * 8 + i;
        float* Crow = C + r * (long)N + bn + tx * 8;
        #pragma unroll
        for (int j = 0; j < 8; j += 4) {
            float4 v;
            float v0 = acc[i][j], v1 = acc[i][j + 1], v2 = acc[i][j + 2], v3 = acc[i][j + 3];
            if (EPI) {
                const float* bp = bias + bn + tx * 8 + j;
                v0 = fmaxf(v0 + bp[0], 0.f);
                v1 = fmaxf(v1 + bp[1], 0.f);
                v2 = fmaxf(v2 + bp[2], 0.f);
                v3 = fmaxf(v3 + bp[3], 0.f);
            }
            v.x = v0; v.y = v1; v.z = v2; v.w = v3;
            *(float4*)&Crow[j] = v;
        }
    }
}

// ---------------- colsum final (g_part -> g_deg) ----------------
__global__ __launch_bounds__(128) void colsum_final_k(const float* __restrict__ H) {
    int idx = blockIdx.x * blockDim.x + threadIdx.x;
    if (idx >= CC * NN) return;
    int c = idx / NN, m = idx % NN;
    float s = 0.f;
    #pragma unroll
    for (int j = 0; j < 16; j++)
        s += g_part[(long)c * 16 * NN + (long)j * NN + m];
    s -= H[(long)c * NN * NN + (long)m * NN + m];
    g_deg[idx] = s;
}

// ---------------- mid norm -> fp16 ----------------
__global__ __launch_bounds__(256) void norm_mid_k(const float* __restrict__ H) {
    long i = (long)blockIdx.x * blockDim.x + threadIdx.x;
    if (i >= (long)CC * NN * NN) return;
    int c = (int)(i / ((long)NN * NN));
    long rem = i % ((long)NN * NN);
    int n = (int)(rem / NN), m = (int)(rem % NN);
    float d = g_deg[c * NN + m];
    float v = (n == m || d <= 0.f) ? 0.f : H[i] / d;
    g_Hf[i] = __float2half_rn(v);
}

// ------- final double norm fused with transpose -> fp16 HsT ----
__global__ __launch_bounds__(256) void norm_final_t_k(const float* __restrict__ H) {
    __shared__ float t[32][33];
    const int c = blockIdx.z;
    const int x0 = blockIdx.x * 32, y0 = blockIdx.y * 32;
    const int tx = threadIdx.x & 31, ty = threadIdx.x >> 5;
    const float d1 = g_deg[c * NN + x0 + tx];
    const float inv1 = (d1 > 0.f) ? 1.f / d1 : 0.f;
    const float inv2 = (d1 > 0.f) ? 0.5f : 1.f;
    const float* Hc = H + (long)c * NN * NN;
    #pragma unroll
    for (int i = 0; i < 4; i++) {
        int n = y0 + ty + 8 * i, m = x0 + tx;
        float v = Hc[(long)n * NN + m];
        v = (n == m) ? 1.f : v * inv1;
        t[ty + 8 * i][tx] = v * inv2;
    }
    __syncthreads();
    __half* dst = g_HsT + (long)c * NN * NN;
    #pragma unroll
    for (int i = 0; i < 4; i++) {
        int rr = ty + 8 * i;
        dst[(long)(x0 + rr) * NN + y0 + tx] = __float2half_rn(t[tx][rr]);
    }
}

// ---------------- split-K reduce for agg ----------------
__global__ __launch_bounds__(256) void aggreduce_k() {
    long i4 = ((long)blockIdx.x * blockDim.x + threadIdx.x) * 4;
    if (i4 >= (long)CC * NN * DD) return;
    float4 s = *(const float4*)&g_aggp[i4];
    #pragma unroll
    for (int ks = 1; ks < KS; ks++) {
        const float4 v = *(const float4*)&g_aggp[(long)ks * CC * NN * DD + i4];
        s.x += v.x; s.y += v.y; s.z += v.z; s.w += v.w;
    }
    *(float4*)&g_agg[i4] = s;
}

// ---------------- lin1 / lin2 ----------------
__global__ __launch_bounds__(128) void lin1_k(const float* __restrict__ w,
                                              const float* __restrict__ b) {
    __shared__ float xr[CC * HD];
    int m = blockIdx.x, t = threadIdx.x;
    xr[t]      = g_X[(long)m * HD + t];
    xr[HD + t] = g_X[(long)NN * HD + (long)m * HD + t];
    __syncthreads();
    float acc = b[t];
    #pragma unroll 8
    for (int k = 0; k < CC * HD; k++)
        acc = fmaf(xr[k], w[k * HD + t], acc);
    g_X2[(long)m * HD + t] = fmaxf(acc, 0.f);
}
__global__ __launch_bounds__(128) void lin2_k(const int* __restrict__ idx,
                                              const float* __restrict__ w,
                                              const float* __restrict__ b,
                                              float* __restrict__ y, int ncat) {
    int i = blockIdx.x * blockDim.x + threadIdx.x;
    if (i >= ncat * NCLS) return;
    int row = i / NCLS, j = i % NCLS;
    const float* x = g_X2 + (long)idx[row] * HD;
    float acc = b[j];
    #pragma unroll 8
    for (int k = 0; k < HD; k++)
        acc = fmaf(x[k], w[k * NCLS + j], acc);
    y[i] = acc;
}

// ---------------- launch ----------------
extern "C" void kernel_launch(void* const* d_in, const int* in_sizes, int n_in,
                              void* d_out, int out_size) {
    const float *A = 0, *h = 0, *W_conv = 0, *gcn_w = 0, *gcn_b = 0;
    const float *lin1_w = 0, *lin1_b = 0, *lin2_w = 0, *lin2_b = 0;
    const int* catidx = 0;
    int ncat = 0;
    for (int i = 0; i < n_in; i++) {
        int s = in_sizes[i];
        const void* p = d_in[i];
        if      (s == RR * NN * NN) A = (const float*)p;
        else if (s == NN * DD)      h = (const float*)p;
        else if (s == 3 * CC * RR)  W_conv = (const float*)p;
        else if (s == DD * HD) { if (!gcn_w) gcn_w = (const float*)p; else lin1_w = (const float*)p; }
        else if (s == HD)      { if (!gcn_b) gcn_b = (const float*)p; else lin1_b = (const float*)p; }
        else if (s == HD * NCLS) lin2_w = (const float*)p;
        else if (s == NCLS)      lin2_b = (const float*)p;
        else { catidx = (const int*)p; ncat = s; }
    }
    float* y = (float*)d_out;

    float *H, *H2, *agg, *aggp, *X;
    __half *Q0f, *Q1t, *Q2t, *Hf, *HsT, *hT;
    cudaGetSymbolAddress((void**)&H,    g_H);
    cudaGetSymbolAddress((void**)&H2,   g_H2);
    cudaGetSymbolAddress((void**)&agg,  g_agg);
    cudaGetSymbolAddress((void**)&aggp, g_aggp);
    cudaGetSymbolAddress((void**)&X,    g_X);
    cudaGetSymbolAddress((void**)&Q0f,  g_Q0f);
    cudaGetSymbolAddress((void**)&Q1t,  g_Q1t);
    cudaGetSymbolAddress((void**)&Q2t,  g_Q2t);
    cudaGetSymbolAddress((void**)&Hf,   g_Hf);
    cudaGetSymbolAddress((void**)&HsT,  g_HsT);
    cudaGetSymbolAddress((void**)&hT,   g_hT);

    static int smem_set = 0;
    if (!smem_set) {
        cudaFuncSetAttribute(gemm16_k<true>,  cudaFuncAttributeMaxDynamicSharedMemorySize, SMEM16);
        cudaFuncSetAttribute(gemm16_k<false>, cudaFuncAttributeMaxDynamicSharedMemorySize, SMEM16);
        smem_set = 1;
    }

    const long NNNN = (long)NN * NN;

    softmax_k<<<1, 32>>>(W_conv);
    qcombine_t_k<<<dim3(NN / 32, NN / 32), 256>>>(A);
    htrans_k<<<dim3(DD / 32, NN / 32), 256>>>(h);

    // GEMM1: H = Q0 @ Q1^T  (+ fused tile column sums)
    gemm16_k<true><<<dim3(16, 16, CC), 128, SMEM16>>>(Q0f, Q1t, H, NN,
                                                      NNNN, NNNN, NNNN, 0, 32);
    colsum_final_k<<<CC * NN / 128, 128>>>(H);
    norm_mid_k<<<(int)(CC * NNNN / 256), 256>>>(H);

    // GEMM2: H2 = Hn @ Q2^T  (+ fused tile column sums)
    gemm16_k<true><<<dim3(16, 16, CC), 128, SMEM16>>>(Hf, Q2t, H2, NN,
                                                      NNNN, NNNN, NNNN, 0, 32);
    colsum_final_k<<<CC * NN / 128, 128>>>(H2);
    norm_final_t_k<<<dim3(NN / 32, NN / 32, CC), 256>>>(H2);

    // AGG (split-K x4): aggp[ks*CC+c] = HsT[c] @ hT^T over K-slice
    gemm16_k<false><<<dim3(DD / 128, NN / 128, CC * KS), 128, SMEM16>>>(
        HsT, hT, aggp, DD, NNNN, 0, (long)NN * DD, CC, 32 / KS);
    aggreduce_k<<<(int)(CC * NN * DD / 4 / 256), 256>>>();

    // X = relu(agg @ gcn_w + gcn_b)
    {
        dim3 g(HD / 128, NN / 128, CC);
        sgemm_k<true><<<g, 256>>>(agg, gcn_w, X, gcn_b,
                                  NN, HD, DD, (long)NN * DD, 0, (long)NN * HD);
    }
    lin1_k<<<NN, 128>>>(lin1_w, lin1_b);
    lin2_k<<<(ncat * NCLS + 127) / 128, 128>>>(catidx, lin2_w, lin2_b, y, ncat);
}